// round 8
// baseline (speedup 1.0000x reference)
#include <cuda_runtime.h>
#include <cstdint>

// ---------------- problem constants ----------------
#define BATCH   2048
#define CSUB    256
#define KDIM    256
#define NDIM    256
#define MTILE   128

#define HS_STR  260          // floats; 260%32==4 -> conflict-free A fragment LDS
#define BS_STR  264          // floats; 264%32==8 -> conflict-free B fragment LDS

#define A_BYTES   (128 * HS_STR * 4)            // 133120
#define B_OFF     A_BYTES
#define B_BYTES   (32 * BS_STR * 4)             // 33792 per buffer (x2)
#define BIAS_OFF  (B_OFF + 2 * B_BYTES)         // 200704
#define W3_OFF    (BIAS_OFF + 1024)
#define RS_OFF    (W3_OFF + 1024)
#define SMEM_BYTES (RS_OFF + 512)               // 203264

// ---------------- scratch (pre-rounded tf32 operands) ----------------
__device__ float g_W1t[CSUB * KDIM * NDIM];     // 64 MiB
__device__ float g_W2t[CSUB * KDIM * NDIM];     // 64 MiB
__device__ float g_xt[BATCH * KDIM];            // 2 MiB

// ---------------- helpers ----------------
__device__ __forceinline__ uint32_t f2tf32(float f) {
    uint32_t u;
    asm("cvt.rna.tf32.f32 %0, %1;" : "=r"(u) : "f"(f));
    return u;
}

__device__ __forceinline__ uint32_t smem_u32(const void* p) {
    uint32_t a;
    asm("{ .reg .u64 t; cvta.to.shared.u64 t, %1; cvt.u32.u64 %0, t; }" : "=r"(a) : "l"(p));
    return a;
}

__device__ __forceinline__ void cp16(uint32_t dst, const void* src) {
    asm volatile("cp.async.cg.shared.global [%0], [%1], 16;" :: "r"(dst), "l"(src) : "memory");
}
#define CP_COMMIT() asm volatile("cp.async.commit_group;" ::: "memory")
#define CP_WAIT1()  asm volatile("cp.async.wait_group 1;"  ::: "memory")
#define CP_WAIT0()  asm volatile("cp.async.wait_group 0;"  ::: "memory")

__device__ __forceinline__ void mma_tf32(float* d,
                                         uint32_t a0, uint32_t a1, uint32_t a2, uint32_t a3,
                                         uint32_t b0, uint32_t b1) {
    asm volatile(
        "mma.sync.aligned.m16n8k8.row.col.f32.tf32.tf32.f32 "
        "{%0,%1,%2,%3}, {%4,%5,%6,%7}, {%8,%9}, {%0,%1,%2,%3};"
        : "+f"(d[0]), "+f"(d[1]), "+f"(d[2]), "+f"(d[3])
        : "r"(a0), "r"(a1), "r"(a2), "r"(a3), "r"(b0), "r"(b1));
}

// ---------------- prepass: round to tf32 (rna), elementwise ----------------
__global__ void round_tf32_kernel(const float* __restrict__ src, int sel, int n4) {
    float* dst = (sel == 0) ? g_W1t : (sel == 1) ? g_W2t : g_xt;
    int i = blockIdx.x * blockDim.x + threadIdx.x;
    const int stride = gridDim.x * blockDim.x;
    for (; i < n4; i += stride) {
        float4 v = reinterpret_cast<const float4*>(src)[i];
        uint4 u;
        u.x = f2tf32(v.x); u.y = f2tf32(v.y);
        u.z = f2tf32(v.z); u.w = f2tf32(v.w);
        reinterpret_cast<uint4*>(dst)[i] = u;
    }
}

// ---------------- staging ----------------
__device__ __forceinline__ void stage_B(uint32_t sb, int bufsel, const float* src, int tid) {
    const uint32_t base = sb + B_OFF + bufsel * B_BYTES;
    #pragma unroll
    for (int i = 0; i < 4; ++i) {
        const int u  = tid + i * 512;       // 2048 x 16B units = 32 rows x 1024 B
        const int k  = u >> 6;
        const int n4 = u & 63;
        cp16(base + k * (BS_STR * 4) + n4 * 16, src + u * 4);
    }
    CP_COMMIT();
}

// ---------------- main kernel ----------------
__global__ __launch_bounds__(512, 1)
void rfprism_main(const float* __restrict__ b1,
                  const float* __restrict__ b2,
                  const float* __restrict__ W3,
                  const float* __restrict__ b3,
                  float* __restrict__ out) {
    extern __shared__ char smem[];
    const uint32_t sb = smem_u32(smem);
    float* Hs     = (float*)smem;
    float* sBias  = (float*)(smem + BIAS_OFF);
    float* sW3v   = (float*)(smem + W3_OFF);
    float* rowsum = (float*)(smem + RS_OFF);

    const int tid  = threadIdx.x;
    const int warp = tid >> 5;
    const int lane = tid & 31;
    const int c    = blockIdx.y;
    const int b0   = blockIdx.x * MTILE;
    const int wm   = warp >> 2;
    const int wn   = warp & 3;
    const int g    = lane >> 2;
    const int tig  = lane & 3;

    // ---- prologue: async-copy A (x tile) + first two W1 chunks ----
    {
        #pragma unroll
        for (int i = 0; i < 16; ++i) {
            const int u   = tid + i * 512;      // 0..8191
            const int row = u >> 6;             // 64 units (1024 B) per row
            const int k4  = u & 63;
            cp16(sb + row * (HS_STR * 4) + k4 * 16,
                 g_xt + (size_t)(b0 + row) * KDIM + k4 * 4);
        }
        CP_COMMIT();
    }
    stage_B(sb, 0, g_W1t + (size_t)c * (KDIM * NDIM), tid);
    stage_B(sb, 1, g_W1t + (size_t)c * (KDIM * NDIM) + 8192, tid);

    if (tid < 64) {
        ((float4*)sBias)[tid] = ((const float4*)(b1 + (size_t)c * 256))[tid];
    } else if (tid < 128) {
        ((float4*)sW3v)[tid - 64] = ((const float4*)(W3 + (size_t)c * 256))[tid - 64];
    } else if (tid < 256) {
        rowsum[tid - 128] = 0.0f;
    }

    float acc[2][8][4];
    #pragma unroll
    for (int m = 0; m < 2; ++m)
        #pragma unroll
        for (int t = 0; t < 8; ++t)
            #pragma unroll
            for (int r = 0; r < 4; ++r)
                acc[m][t][r] = 0.0f;

    const int nfrag = wn * 64 + g;   // base column for B fragments

    // ---- pipelined mainloop over 16 chunks (8 per layer) ----
    #pragma unroll 1
    for (int kk = 0; kk < 16; ++kk) {
        if (kk < 15) { CP_WAIT1(); } else { CP_WAIT0(); }
        __syncthreads();

        const float* sBb = (const float*)(smem + B_OFF + (kk & 1) * B_BYTES);

        // ---- software-pipelined fragment compute: B double-buffered in regs ----
        uint32_t bf[2][8][2];
        #pragma unroll
        for (int t = 0; t < 8; ++t) {          // preload k8=0 B frags
            const int n = nfrag + t * 8;
            bf[0][t][0] = __float_as_uint(sBb[(tig)     * BS_STR + n]);
            bf[0][t][1] = __float_as_uint(sBb[(tig + 4) * BS_STR + n]);
        }

        #pragma unroll
        for (int k8 = 0; k8 < 4; ++k8) {
            const int kb  = k8 * 8;
            const int ka  = (kk & 7) * 32 + kb;
            const int cur = k8 & 1;

            // A frags for this k8 (8 LDS; latency covered by B-next issue burst)
            uint32_t a[2][4];
            #pragma unroll
            for (int m = 0; m < 2; ++m) {
                const int r = wm * 32 + m * 16;
                a[m][0] = __float_as_uint(Hs[(r + g)     * HS_STR + ka + tig]);
                a[m][1] = __float_as_uint(Hs[(r + g + 8) * HS_STR + ka + tig]);
                a[m][2] = __float_as_uint(Hs[(r + g)     * HS_STR + ka + tig + 4]);
                a[m][3] = __float_as_uint(Hs[(r + g + 8) * HS_STR + ka + tig + 4]);
            }

            // B frags for NEXT k8 (issued before MMAs -> hidden under them)
            if (k8 < 3) {
                const int kb2 = kb + 8;
                #pragma unroll
                for (int t = 0; t < 8; ++t) {
                    const int n = nfrag + t * 8;
                    bf[cur ^ 1][t][0] = __float_as_uint(sBb[(kb2 + tig)     * BS_STR + n]);
                    bf[cur ^ 1][t][1] = __float_as_uint(sBb[(kb2 + tig + 4) * BS_STR + n]);
                }
            }

            #pragma unroll
            for (int m = 0; m < 2; ++m)
                #pragma unroll
                for (int t = 0; t < 8; ++t)
                    mma_tf32(acc[m][t], a[m][0], a[m][1], a[m][2], a[m][3],
                             bf[cur][t][0], bf[cur][t][1]);
        }
        __syncthreads();   // all reads of buf[kk&1] (and, at kk==7, of Hs) done

        // issue copy of chunk kk+2 into the buffer just freed (overlaps next compute)
        if (kk + 2 < 16) {
            const int t2 = kk + 2;
            const float* W = (t2 < 8) ? g_W1t : g_W2t;
            stage_B(sb, kk & 1, W + (size_t)c * (KDIM * NDIM) + (size_t)(t2 & 7) * 8192, tid);
        }

        if (kk == 7) {
            // epilogue 1: Hs = tf32(relu(acc + b1)); own rows only
            #pragma unroll
            for (int m = 0; m < 2; ++m) {
                const int r0 = wm * 32 + m * 16 + g;
                const int r1 = r0 + 8;
                #pragma unroll
                for (int t = 0; t < 8; ++t) {
                    const int c0 = wn * 64 + t * 8 + 2 * tig;
                    float v00 = fmaxf(acc[m][t][0] + sBias[c0],     0.0f);
                    float v01 = fmaxf(acc[m][t][1] + sBias[c0 + 1], 0.0f);
                    float v10 = fmaxf(acc[m][t][2] + sBias[c0],     0.0f);
                    float v11 = fmaxf(acc[m][t][3] + sBias[c0 + 1], 0.0f);
                    Hs[r0 * HS_STR + c0]     = __uint_as_float(f2tf32(v00));
                    Hs[r0 * HS_STR + c0 + 1] = __uint_as_float(f2tf32(v01));
                    Hs[r1 * HS_STR + c0]     = __uint_as_float(f2tf32(v10));
                    Hs[r1 * HS_STR + c0 + 1] = __uint_as_float(f2tf32(v11));
                }
            }
            __syncthreads();            // Hs writes + b1 reads done everywhere
            if (tid < 64)               // b2 replaces b1 (read only in epilogue 2)
                ((float4*)sBias)[tid] = ((const float4*)(b2 + (size_t)c * 256))[tid];
            #pragma unroll
            for (int m = 0; m < 2; ++m)
                #pragma unroll
                for (int t = 0; t < 8; ++t)
                    #pragma unroll
                    for (int r = 0; r < 4; ++r)
                        acc[m][t][r] = 0.0f;
        }
    }

    // ---- epilogue 2 + layer 3: rowsum += relu(acc + b2) . W3 ----
    #pragma unroll
    for (int m = 0; m < 2; ++m) {
        const int r0 = wm * 32 + m * 16 + g;
        const int r1 = r0 + 8;
        float s0 = 0.0f, s1 = 0.0f;
        #pragma unroll
        for (int t = 0; t < 8; ++t) {
            const int c0 = wn * 64 + t * 8 + 2 * tig;
            const float w0 = sW3v[c0], w1 = sW3v[c0 + 1];
            const float bb0 = sBias[c0], bb1 = sBias[c0 + 1];
            s0 += fmaxf(acc[m][t][0] + bb0, 0.0f) * w0
                + fmaxf(acc[m][t][1] + bb1, 0.0f) * w1;
            s1 += fmaxf(acc[m][t][2] + bb0, 0.0f) * w0
                + fmaxf(acc[m][t][3] + bb1, 0.0f) * w1;
        }
        s0 += __shfl_xor_sync(0xffffffffu, s0, 1);
        s0 += __shfl_xor_sync(0xffffffffu, s0, 2);
        s1 += __shfl_xor_sync(0xffffffffu, s1, 1);
        s1 += __shfl_xor_sync(0xffffffffu, s1, 2);
        if (tig == 0) {
            atomicAdd(&rowsum[r0], s0);
            atomicAdd(&rowsum[r1], s1);
        }
    }

    __syncthreads();
    if (tid < MTILE)
        out[(size_t)(b0 + tid) * CSUB + c] = rowsum[tid] + b3[c];
}

extern "C" void kernel_launch(void* const* d_in, const int* in_sizes, int n_in,
                              void* d_out, int out_size) {
    (void)in_sizes; (void)n_in; (void)out_size;
    const float* x  = (const float*)d_in[0];
    const float* W1 = (const float*)d_in[1];
    const float* b1 = (const float*)d_in[2];
    const float* W2 = (const float*)d_in[3];
    const float* b2 = (const float*)d_in[4];
    const float* W3 = (const float*)d_in[5];
    const float* b3 = (const float*)d_in[6];
    float* out = (float*)d_out;

    // prepass: tf32-round W1, W2, x into scratch
    const int nW4 = (CSUB * KDIM * NDIM) / 4;    // 4,194,304
    const int nX4 = (BATCH * KDIM) / 4;          // 131,072
    round_tf32_kernel<<<4096, 256>>>(W1, 0, nW4);
    round_tf32_kernel<<<4096, 256>>>(W2, 1, nW4);
    round_tf32_kernel<<<512, 256>>>(x,  2, nX4);

    cudaFuncSetAttribute(rfprism_main,
                         cudaFuncAttributeMaxDynamicSharedMemorySize, SMEM_BYTES);
    dim3 grid(BATCH / MTILE, CSUB);   // (16, 256)
    rfprism_main<<<grid, 512, SMEM_BYTES>>>(b1, b2, W3, b3, out);
}

// round 10
// speedup vs baseline: 1.1321x; 1.1321x over previous
#include <cuda_runtime.h>
#include <cstdint>

// ---------------- problem constants ----------------
#define BATCH   2048
#define CSUB    256
#define KDIM    256
#define NDIM    256
#define MTILE   64           // 2 CTAs / SM now
#define CHUNK_K 16
#define NCHUNK  (KDIM / CHUNK_K)     // 16 chunks per layer, 32 total

#define HS_STR  260          // floats; (4g+tig)%32 distinct -> conflict-free A frags
#define BS_STR  264          // floats; (8tig+g)%32 distinct -> conflict-free B frags

#define A_BYTES   (MTILE * HS_STR * 4)          // 66560
#define B_OFF     A_BYTES
#define B_BYTES   (CHUNK_K * BS_STR * 4)        // 16896 per buffer (x2)
#define BIAS_OFF  (B_OFF + 2 * B_BYTES)         // 100352
#define W3_OFF    (BIAS_OFF + 1024)
#define RS_OFF    (W3_OFF + 1024)
#define SMEM_BYTES (RS_OFF + 256)               // 102656  (2 per SM: 205312 < 227KB)

// ---------------- scratch (pre-rounded tf32 operands) ----------------
__device__ float g_W1t[CSUB * KDIM * NDIM];     // 64 MiB
__device__ float g_W2t[CSUB * KDIM * NDIM];     // 64 MiB
__device__ float g_xt[BATCH * KDIM];            // 2 MiB

// ---------------- helpers ----------------
__device__ __forceinline__ uint32_t f2tf32(float f) {
    uint32_t u;
    asm("cvt.rna.tf32.f32 %0, %1;" : "=r"(u) : "f"(f));
    return u;
}

__device__ __forceinline__ uint32_t smem_u32(const void* p) {
    uint32_t a;
    asm("{ .reg .u64 t; cvta.to.shared.u64 t, %1; cvt.u32.u64 %0, t; }" : "=r"(a) : "l"(p));
    return a;
}

__device__ __forceinline__ void cp16(uint32_t dst, const void* src) {
    asm volatile("cp.async.cg.shared.global [%0], [%1], 16;" :: "r"(dst), "l"(src) : "memory");
}
#define CP_COMMIT() asm volatile("cp.async.commit_group;" ::: "memory")
#define CP_WAIT1()  asm volatile("cp.async.wait_group 1;"  ::: "memory")
#define CP_WAIT0()  asm volatile("cp.async.wait_group 0;"  ::: "memory")

__device__ __forceinline__ void mma_tf32(float* d,
                                         uint32_t a0, uint32_t a1, uint32_t a2, uint32_t a3,
                                         uint32_t b0, uint32_t b1) {
    asm volatile(
        "mma.sync.aligned.m16n8k8.row.col.f32.tf32.tf32.f32 "
        "{%0,%1,%2,%3}, {%4,%5,%6,%7}, {%8,%9}, {%0,%1,%2,%3};"
        : "+f"(d[0]), "+f"(d[1]), "+f"(d[2]), "+f"(d[3])
        : "r"(a0), "r"(a1), "r"(a2), "r"(a3), "r"(b0), "r"(b1));
}

// ---------------- prepass: round to tf32 (rna), elementwise ----------------
__global__ void round_tf32_kernel(const float* __restrict__ src, int sel, int n4) {
    float* dst = (sel == 0) ? g_W1t : (sel == 1) ? g_W2t : g_xt;
    int i = blockIdx.x * blockDim.x + threadIdx.x;
    const int stride = gridDim.x * blockDim.x;
    for (; i < n4; i += stride) {
        float4 v = reinterpret_cast<const float4*>(src)[i];
        uint4 u;
        u.x = f2tf32(v.x); u.y = f2tf32(v.y);
        u.z = f2tf32(v.z); u.w = f2tf32(v.w);
        reinterpret_cast<uint4*>(dst)[i] = u;
    }
}

// ---------------- staging: one 16k x 256n W chunk ----------------
__device__ __forceinline__ void stage_B(uint32_t sb, int bufsel, const float* src, int tid) {
    const uint32_t base = sb + B_OFF + bufsel * B_BYTES;
    #pragma unroll
    for (int i = 0; i < 4; ++i) {
        const int u  = tid + i * 256;       // 1024 x 16B units = 16 rows x 1024 B
        const int k  = u >> 6;
        const int n4 = u & 63;
        cp16(base + k * (BS_STR * 4) + n4 * 16, src + u * 4);
    }
    CP_COMMIT();
}

// ---------------- main kernel ----------------
__global__ __launch_bounds__(256, 2)
void rfprism_main(const float* __restrict__ b1,
                  const float* __restrict__ b2,
                  const float* __restrict__ W3,
                  const float* __restrict__ b3,
                  float* __restrict__ out) {
    extern __shared__ char smem[];
    const uint32_t sb = smem_u32(smem);
    float* Hs     = (float*)smem;
    float* sBias  = (float*)(smem + BIAS_OFF);
    float* sW3v   = (float*)(smem + W3_OFF);
    float* rowsum = (float*)(smem + RS_OFF);

    const int tid  = threadIdx.x;
    const int warp = tid >> 5;          // 0..7
    const int lane = tid & 31;
    const int c    = blockIdx.y;
    const int b0   = blockIdx.x * MTILE;
    const int wm   = warp >> 2;         // 0..1 (M)
    const int wn   = warp & 3;          // 0..3 (N)
    const int g    = lane >> 2;         // 0..7
    const int tig  = lane & 3;          // 0..3

    // ---- prologue: async-copy A (x tile: 64 rows x 64 units) + first two W1 chunks ----
    {
        #pragma unroll
        for (int i = 0; i < 16; ++i) {
            const int u   = tid + i * 256;      // 0..4095
            const int row = u >> 6;             // 0..63
            const int k4  = u & 63;
            cp16(sb + row * (HS_STR * 4) + k4 * 16,
                 g_xt + (size_t)(b0 + row) * KDIM + k4 * 4);
        }
        CP_COMMIT();
    }
    stage_B(sb, 0, g_W1t + (size_t)c * (KDIM * NDIM), tid);
    stage_B(sb, 1, g_W1t + (size_t)c * (KDIM * NDIM) + CHUNK_K * NDIM, tid);

    if (tid < 64) {
        ((float4*)sBias)[tid] = ((const float4*)(b1 + (size_t)c * 256))[tid];
    } else if (tid < 128) {
        ((float4*)sW3v)[tid - 64] = ((const float4*)(W3 + (size_t)c * 256))[tid - 64];
    } else if (tid < 192) {
        rowsum[tid - 128] = 0.0f;
    }

    float acc[2][8][4];
    #pragma unroll
    for (int m = 0; m < 2; ++m)
        #pragma unroll
        for (int t = 0; t < 8; ++t)
            #pragma unroll
            for (int r = 0; r < 4; ++r)
                acc[m][t][r] = 0.0f;

    // ---- pipelined mainloop over 32 chunks (16 per layer) ----
    #pragma unroll 1
    for (int kk = 0; kk < 2 * NCHUNK; ++kk) {
        if (kk < 2 * NCHUNK - 1) { CP_WAIT1(); } else { CP_WAIT0(); }
        __syncthreads();

        const float* sBb = (const float*)(smem + B_OFF + (kk & 1) * B_BYTES);

        #pragma unroll
        for (int k8 = 0; k8 < CHUNK_K / 8; ++k8) {          // 2 k-steps of 8
            const int kb = k8 * 8;
            uint32_t bf[8][2];
            #pragma unroll
            for (int t = 0; t < 8; ++t) {
                const int n = wn * 64 + t * 8 + g;
                bf[t][0] = __float_as_uint(sBb[(kb + tig)     * BS_STR + n]);
                bf[t][1] = __float_as_uint(sBb[(kb + tig + 4) * BS_STR + n]);
            }
            const int ka = (kk & (NCHUNK - 1)) * CHUNK_K + kb;
            #pragma unroll
            for (int m = 0; m < 2; ++m) {
                const int r = wm * 32 + m * 16;
                uint32_t a0 = __float_as_uint(Hs[(r + g)     * HS_STR + ka + tig]);
                uint32_t a1 = __float_as_uint(Hs[(r + g + 8) * HS_STR + ka + tig]);
                uint32_t a2 = __float_as_uint(Hs[(r + g)     * HS_STR + ka + tig + 4]);
                uint32_t a3 = __float_as_uint(Hs[(r + g + 8) * HS_STR + ka + tig + 4]);
                #pragma unroll
                for (int t = 0; t < 8; ++t)
                    mma_tf32(acc[m][t], a0, a1, a2, a3, bf[t][0], bf[t][1]);
            }
        }
        __syncthreads();   // all reads of buf[kk&1] (and, at layer end, of Hs) done

        // issue copy of chunk kk+2 into the buffer just freed (overlaps next compute)
        if (kk + 2 < 2 * NCHUNK) {
            const int t2 = kk + 2;
            const float* W = (t2 < NCHUNK) ? g_W1t : g_W2t;
            stage_B(sb, kk & 1,
                    W + (size_t)c * (KDIM * NDIM) + (size_t)(t2 & (NCHUNK - 1)) * (CHUNK_K * NDIM),
                    tid);
        }

        if (kk == NCHUNK - 1) {
            // epilogue 1: Hs = tf32(relu(acc + b1)); own rows only
            #pragma unroll
            for (int m = 0; m < 2; ++m) {
                const int r0 = wm * 32 + m * 16 + g;
                const int r1 = r0 + 8;
                #pragma unroll
                for (int t = 0; t < 8; ++t) {
                    const int c0 = wn * 64 + t * 8 + 2 * tig;
                    float v00 = fmaxf(acc[m][t][0] + sBias[c0],     0.0f);
                    float v01 = fmaxf(acc[m][t][1] + sBias[c0 + 1], 0.0f);
                    float v10 = fmaxf(acc[m][t][2] + sBias[c0],     0.0f);
                    float v11 = fmaxf(acc[m][t][3] + sBias[c0 + 1], 0.0f);
                    Hs[r0 * HS_STR + c0]     = __uint_as_float(f2tf32(v00));
                    Hs[r0 * HS_STR + c0 + 1] = __uint_as_float(f2tf32(v01));
                    Hs[r1 * HS_STR + c0]     = __uint_as_float(f2tf32(v10));
                    Hs[r1 * HS_STR + c0 + 1] = __uint_as_float(f2tf32(v11));
                }
            }
            __syncthreads();            // Hs writes + b1 reads done everywhere
            if (tid < 64)               // b2 replaces b1 (read only in epilogue 2)
                ((float4*)sBias)[tid] = ((const float4*)(b2 + (size_t)c * 256))[tid];
            #pragma unroll
            for (int m = 0; m < 2; ++m)
                #pragma unroll
                for (int t = 0; t < 8; ++t)
                    #pragma unroll
                    for (int r = 0; r < 4; ++r)
                        acc[m][t][r] = 0.0f;
        }
    }

    // ---- epilogue 2 + layer 3: rowsum += relu(acc + b2) . W3 ----
    #pragma unroll
    for (int m = 0; m < 2; ++m) {
        const int r0 = wm * 32 + m * 16 + g;
        const int r1 = r0 + 8;
        float s0 = 0.0f, s1 = 0.0f;
        #pragma unroll
        for (int t = 0; t < 8; ++t) {
            const int c0 = wn * 64 + t * 8 + 2 * tig;
            const float w0 = sW3v[c0], w1 = sW3v[c0 + 1];
            const float bb0 = sBias[c0], bb1 = sBias[c0 + 1];
            s0 += fmaxf(acc[m][t][0] + bb0, 0.0f) * w0
                + fmaxf(acc[m][t][1] + bb1, 0.0f) * w1;
            s1 += fmaxf(acc[m][t][2] + bb0, 0.0f) * w0
                + fmaxf(acc[m][t][3] + bb1, 0.0f) * w1;
        }
        s0 += __shfl_xor_sync(0xffffffffu, s0, 1);
        s0 += __shfl_xor_sync(0xffffffffu, s0, 2);
        s1 += __shfl_xor_sync(0xffffffffu, s1, 1);
        s1 += __shfl_xor_sync(0xffffffffu, s1, 2);
        if (tig == 0) {
            atomicAdd(&rowsum[r0], s0);
            atomicAdd(&rowsum[r1], s1);
        }
    }

    __syncthreads();
    if (tid < MTILE)
        out[(size_t)(b0 + tid) * CSUB + c] = rowsum[tid] + b3[c];
}

extern "C" void kernel_launch(void* const* d_in, const int* in_sizes, int n_in,
                              void* d_out, int out_size) {
    (void)in_sizes; (void)n_in; (void)out_size;
    const float* x  = (const float*)d_in[0];
    const float* W1 = (const float*)d_in[1];
    const float* b1 = (const float*)d_in[2];
    const float* W2 = (const float*)d_in[3];
    const float* b2 = (const float*)d_in[4];
    const float* W3 = (const float*)d_in[5];
    const float* b3 = (const float*)d_in[6];
    float* out = (float*)d_out;

    // prepass: tf32-round W1, W2, x into scratch
    const int nW4 = (CSUB * KDIM * NDIM) / 4;    // 4,194,304
    const int nX4 = (BATCH * KDIM) / 4;          // 131,072
    round_tf32_kernel<<<4096, 256>>>(W1, 0, nW4);
    round_tf32_kernel<<<4096, 256>>>(W2, 1, nW4);
    round_tf32_kernel<<<512, 256>>>(x,  2, nX4);

    cudaFuncSetAttribute(rfprism_main,
                         cudaFuncAttributeMaxDynamicSharedMemorySize, SMEM_BYTES);
    dim3 grid(BATCH / MTILE, CSUB);   // (32, 256)
    rfprism_main<<<grid, 256, SMEM_BYTES>>>(b1, b2, W3, b3, out);
}

// round 11
// speedup vs baseline: 2.1739x; 1.9202x over previous
#include <cuda_runtime.h>
#include <cuda_fp16.h>
#include <cstdint>

// ---------------- problem constants ----------------
#define BATCH   2048
#define CSUB    256
#define KDIM    256
#define NDIM    256
#define MTILE   64
#define CHUNK_K 32
#define NCH     8            // chunks per layer (256/32)

#define HSB     528          // row stride BYTES for A and B tiles (132 words = 4 mod 32)

#define A_OFF     0
#define A_BYTES   (MTILE * HSB)          // 33792
#define B_OFF     A_BYTES
#define B_BYTES   (CHUNK_K * HSB)        // 16896 per buffer (x2)
#define BIAS1_OFF (B_OFF + 2 * B_BYTES)  // 67584
#define BIAS2_OFF (BIAS1_OFF + 1024)
#define W3_OFF    (BIAS2_OFF + 1024)
#define RS_OFF    (W3_OFF + 1024)
#define SMEM_BYTES (RS_OFF + 256)        // 70912 -> 2 CTAs/SM

// ---------------- scratch (pre-converted fp16 operands) ----------------
__device__ __half g_W1h[CSUB * KDIM * NDIM];   // 32 MiB
__device__ __half g_W2h[CSUB * KDIM * NDIM];   // 32 MiB
__device__ __half g_xh[BATCH * KDIM];          // 1 MiB

// ---------------- helpers ----------------
__device__ __forceinline__ uint32_t smem_u32(const void* p) {
    uint32_t a;
    asm("{ .reg .u64 t; cvta.to.shared.u64 t, %1; cvt.u32.u64 %0, t; }" : "=r"(a) : "l"(p));
    return a;
}

__device__ __forceinline__ void cp16(uint32_t dst, const void* src) {
    asm volatile("cp.async.cg.shared.global [%0], [%1], 16;" :: "r"(dst), "l"(src) : "memory");
}
#define CP_COMMIT() asm volatile("cp.async.commit_group;" ::: "memory")
#define CP_WAIT0()  asm volatile("cp.async.wait_group 0;"  ::: "memory")

__device__ __forceinline__ void ldsm_x4(uint32_t* r, uint32_t addr) {
    asm volatile("ldmatrix.sync.aligned.m8n8.x4.shared.b16 {%0,%1,%2,%3}, [%4];"
                 : "=r"(r[0]), "=r"(r[1]), "=r"(r[2]), "=r"(r[3]) : "r"(addr));
}
__device__ __forceinline__ void ldsm_x4_t(uint32_t* r, uint32_t addr) {
    asm volatile("ldmatrix.sync.aligned.m8n8.x4.trans.shared.b16 {%0,%1,%2,%3}, [%4];"
                 : "=r"(r[0]), "=r"(r[1]), "=r"(r[2]), "=r"(r[3]) : "r"(addr));
}

__device__ __forceinline__ void mma_f16(float* d, const uint32_t* a,
                                        uint32_t b0, uint32_t b1) {
    asm volatile(
        "mma.sync.aligned.m16n8k16.row.col.f32.f16.f16.f32 "
        "{%0,%1,%2,%3}, {%4,%5,%6,%7}, {%8,%9}, {%0,%1,%2,%3};"
        : "+f"(d[0]), "+f"(d[1]), "+f"(d[2]), "+f"(d[3])
        : "r"(a[0]), "r"(a[1]), "r"(a[2]), "r"(a[3]), "r"(b0), "r"(b1));
}

// ---------------- prepass: f32 -> fp16 (rn), elementwise ----------------
__global__ void to_fp16_kernel(const float* __restrict__ src, int sel, int n4) {
    __half* dst = (sel == 0) ? g_W1h : (sel == 1) ? g_W2h : g_xh;
    int i = blockIdx.x * blockDim.x + threadIdx.x;
    const int stride = gridDim.x * blockDim.x;
    for (; i < n4; i += stride) {
        float4 v = reinterpret_cast<const float4*>(src)[i];
        __half2 h0 = __floats2half2_rn(v.x, v.y);
        __half2 h1 = __floats2half2_rn(v.z, v.w);
        uint2 o;
        o.x = reinterpret_cast<uint32_t&>(h0);
        o.y = reinterpret_cast<uint32_t&>(h1);
        reinterpret_cast<uint2*>(dst)[i] = o;
    }
}

// ---------------- staging: one 32k x 256n fp16 W chunk ----------------
__device__ __forceinline__ void stage_B(uint32_t base, const __half* src, int tid) {
    #pragma unroll
    for (int i = 0; i < 4; ++i) {
        const int u  = tid + i * 256;       // 1024 units = 32 rows x 32 x 16B
        const int k  = u >> 5;
        const int un = u & 31;
        cp16(base + k * HSB + un * 16, src + k * NDIM + un * 8);
    }
    CP_COMMIT();
}

// ---------------- main kernel ----------------
__global__ __launch_bounds__(256, 2)
void rfprism_main(const float* __restrict__ b1,
                  const float* __restrict__ b2,
                  const float* __restrict__ W3,
                  const float* __restrict__ b3,
                  float* __restrict__ out) {
    extern __shared__ char smem[];
    const uint32_t sb = smem_u32(smem);
    float* sBias1 = (float*)(smem + BIAS1_OFF);
    float* sBias2 = (float*)(smem + BIAS2_OFF);
    float* sW3v   = (float*)(smem + W3_OFF);
    float* rowsum = (float*)(smem + RS_OFF);

    const int tid  = threadIdx.x;
    const int warp = tid >> 5;          // 0..7
    const int lane = tid & 31;
    const int c    = blockIdx.y;
    const int b0   = blockIdx.x * MTILE;
    const int wm   = warp >> 2;         // 0..1 (M)
    const int wn   = warp & 3;          // 0..3 (N)
    const int g    = lane >> 2;         // 0..7
    const int tig  = lane & 3;          // 0..3

    // ldmatrix lane offset (same structure for A tiles and B-trans tiles):
    // tile t = lane>>3: row += (t&1)*8, 16B col block += (t>>1)
    const uint32_t lmoff =
        ((((lane >> 3) & 1) * 8) + (lane & 7)) * HSB + ((lane >> 4) & 1) * 16;

    // ---- prologue: stage A (x tile) + W1 chunk 0; load biases/W3 ----
    #pragma unroll
    for (int i = 0; i < 8; ++i) {
        const int u   = tid + i * 256;      // 0..2047: 64 rows x 32 units
        const int row = u >> 5;
        const int un  = u & 31;
        cp16(sb + A_OFF + row * HSB + un * 16,
             g_xh + (size_t)(b0 + row) * KDIM + un * 8);
    }
    CP_COMMIT();
    stage_B(sb + B_OFF, g_W1h + (size_t)c * (KDIM * NDIM), tid);

    if (tid < 64) {
        ((float4*)sBias1)[tid] = ((const float4*)(b1 + (size_t)c * 256))[tid];
    } else if (tid < 128) {
        ((float4*)sBias2)[tid - 64] = ((const float4*)(b2 + (size_t)c * 256))[tid - 64];
    } else if (tid < 192) {
        ((float4*)sW3v)[tid - 128] = ((const float4*)(W3 + (size_t)c * 256))[tid - 128];
    } else {
        rowsum[tid - 192] = 0.0f;
    }

    float acc[2][8][4];
    #pragma unroll
    for (int m = 0; m < 2; ++m)
        #pragma unroll
        for (int t = 0; t < 8; ++t)
            #pragma unroll
            for (int r = 0; r < 4; ++r)
                acc[m][t][r] = 0.0f;

    // ---- mainloop: 16 chunks (8 per layer), ONE sync per chunk ----
    #pragma unroll 1
    for (int kk = 0; kk < 2 * NCH; ++kk) {
        CP_WAIT0();
        __syncthreads();    // chunk kk data visible; buffer (kk+1)&1 free everywhere

        // stage chunk kk+1 into the buffer freed at kk-1 (lands during compute)
        if (kk + 1 < 2 * NCH) {
            const int t2 = kk + 1;
            const __half* W = (t2 < NCH) ? g_W1h : g_W2h;
            stage_B(sb + B_OFF + (t2 & 1) * B_BYTES,
                    W + (size_t)c * (KDIM * NDIM) + (size_t)(t2 & (NCH - 1)) * (CHUNK_K * NDIM),
                    tid);
        }

        const uint32_t Bbase = sb + B_OFF + (kk & 1) * B_BYTES;

        #pragma unroll
        for (int s = 0; s < 2; ++s) {              // 2 k16 steps per chunk
            const int ka = (kk & (NCH - 1)) * CHUNK_K + s * 16;

            uint32_t a[2][4];
            #pragma unroll
            for (int m = 0; m < 2; ++m)
                ldsm_x4(a[m], sb + A_OFF + (wm * 32 + m * 16) * HSB + lmoff + ka * 2);

            uint32_t bb[4][4];
            #pragma unroll
            for (int j = 0; j < 4; ++j)            // n-tiles (2 per ldsm)
                ldsm_x4_t(bb[j], Bbase + s * 16 * HSB + lmoff + (wn * 64 + j * 16) * 2);

            #pragma unroll
            for (int m = 0; m < 2; ++m)
                #pragma unroll
                for (int t = 0; t < 8; ++t)
                    mma_f16(acc[m][t], a[m],
                            bb[t >> 1][(t & 1) * 2], bb[t >> 1][(t & 1) * 2 + 1]);
        }

        if (kk == NCH - 1) {
            __syncthreads();   // everyone done reading layer-1 A before overwrite
            // epilogue 1: A <- fp16(relu(acc + b1))
            #pragma unroll
            for (int m = 0; m < 2; ++m) {
                const int r0 = wm * 32 + m * 16 + g;
                const int r1 = r0 + 8;
                #pragma unroll
                for (int t = 0; t < 8; ++t) {
                    const int c0 = wn * 64 + t * 8 + 2 * tig;
                    float v00 = fmaxf(acc[m][t][0] + sBias1[c0],     0.0f);
                    float v01 = fmaxf(acc[m][t][1] + sBias1[c0 + 1], 0.0f);
                    float v10 = fmaxf(acc[m][t][2] + sBias1[c0],     0.0f);
                    float v11 = fmaxf(acc[m][t][3] + sBias1[c0 + 1], 0.0f);
                    __half2 h0 = __floats2half2_rn(v00, v01);
                    __half2 h1 = __floats2half2_rn(v10, v11);
                    *(uint32_t*)(smem + A_OFF + r0 * HSB + c0 * 2) =
                        reinterpret_cast<uint32_t&>(h0);
                    *(uint32_t*)(smem + A_OFF + r1 * HSB + c0 * 2) =
                        reinterpret_cast<uint32_t&>(h1);
                }
            }
            #pragma unroll
            for (int m = 0; m < 2; ++m)
                #pragma unroll
                for (int t = 0; t < 8; ++t)
                    #pragma unroll
                    for (int r = 0; r < 4; ++r)
                        acc[m][t][r] = 0.0f;
            // visibility for layer-2 reads: top-of-next-chunk __syncthreads
        }
    }

    // ---- epilogue 2 + layer 3: rowsum += relu(acc + b2) . W3 ----
    #pragma unroll
    for (int m = 0; m < 2; ++m) {
        const int r0 = wm * 32 + m * 16 + g;
        const int r1 = r0 + 8;
        float s0 = 0.0f, s1 = 0.0f;
        #pragma unroll
        for (int t = 0; t < 8; ++t) {
            const int c0 = wn * 64 + t * 8 + 2 * tig;
            const float w0 = sW3v[c0], w1 = sW3v[c0 + 1];
            const float bb0 = sBias2[c0], bb1 = sBias2[c0 + 1];
            s0 += fmaxf(acc[m][t][0] + bb0, 0.0f) * w0
                + fmaxf(acc[m][t][1] + bb1, 0.0f) * w1;
            s1 += fmaxf(acc[m][t][2] + bb0, 0.0f) * w0
                + fmaxf(acc[m][t][3] + bb1, 0.0f) * w1;
        }
        s0 += __shfl_xor_sync(0xffffffffu, s0, 1);
        s0 += __shfl_xor_sync(0xffffffffu, s0, 2);
        s1 += __shfl_xor_sync(0xffffffffu, s1, 1);
        s1 += __shfl_xor_sync(0xffffffffu, s1, 2);
        if (tig == 0) {
            atomicAdd(&rowsum[r0], s0);
            atomicAdd(&rowsum[r1], s1);
        }
    }

    __syncthreads();
    if (tid < MTILE)
        out[(size_t)(b0 + tid) * CSUB + c] = rowsum[tid] + b3[c];
}

extern "C" void kernel_launch(void* const* d_in, const int* in_sizes, int n_in,
                              void* d_out, int out_size) {
    (void)in_sizes; (void)n_in; (void)out_size;
    const float* x  = (const float*)d_in[0];
    const float* W1 = (const float*)d_in[1];
    const float* b1 = (const float*)d_in[2];
    const float* W2 = (const float*)d_in[3];
    const float* b2 = (const float*)d_in[4];
    const float* W3 = (const float*)d_in[5];
    const float* b3 = (const float*)d_in[6];
    float* out = (float*)d_out;

    // prepass: fp16-convert W1, W2, x into scratch
    const int nW4 = (CSUB * KDIM * NDIM) / 4;    // 4,194,304
    const int nX4 = (BATCH * KDIM) / 4;          // 131,072
    to_fp16_kernel<<<4096, 256>>>(W1, 0, nW4);
    to_fp16_kernel<<<4096, 256>>>(W2, 1, nW4);
    to_fp16_kernel<<<512, 256>>>(x,  2, nX4);

    cudaFuncSetAttribute(rfprism_main,
                         cudaFuncAttributeMaxDynamicSharedMemorySize, SMEM_BYTES);
    dim3 grid(BATCH / MTILE, CSUB);   // (32, 256)
    rfprism_main<<<grid, 256, SMEM_BYTES>>>(b1, b2, W3, b3, out);
}

// round 13
// speedup vs baseline: 2.2117x; 1.0174x over previous
#include <cuda_runtime.h>
#include <cuda_fp16.h>
#include <cstdint>

// ---------------- problem constants ----------------
#define BATCH   2048
#define CSUB    256
#define KDIM    256
#define NDIM    256
#define MTILE   64
#define CHUNK_K 64
#define NCH     4            // chunks per layer (256/64)

#define HSB     528          // row stride BYTES for A and B tiles (132 words = 4 mod 32)

#define A_OFF     0
#define A_BYTES   (MTILE * HSB)          // 33792
#define B_OFF     A_BYTES
#define B_BYTES   (CHUNK_K * HSB)        // 33792 per buffer (x2)
#define BIAS1_OFF (B_OFF + 2 * B_BYTES)  // 101376
#define BIAS2_OFF (BIAS1_OFF + 1024)
#define W3_OFF    (BIAS2_OFF + 1024)
#define RS_OFF    (W3_OFF + 1024)
#define SMEM_BYTES (RS_OFF + 256)        // 104704 -> 2 CTAs/SM (209.4KB < 228KB)

// ---------------- scratch (pre-converted fp16 operands) ----------------
__device__ __half g_W1h[CSUB * KDIM * NDIM];   // 32 MiB
__device__ __half g_W2h[CSUB * KDIM * NDIM];   // 32 MiB
__device__ __half g_xh[BATCH * KDIM];          // 1 MiB

// ---------------- helpers ----------------
__device__ __forceinline__ uint32_t smem_u32(const void* p) {
    uint32_t a;
    asm("{ .reg .u64 t; cvta.to.shared.u64 t, %1; cvt.u32.u64 %0, t; }" : "=r"(a) : "l"(p));
    return a;
}

__device__ __forceinline__ void cp16(uint32_t dst, const void* src) {
    asm volatile("cp.async.cg.shared.global [%0], [%1], 16;" :: "r"(dst), "l"(src) : "memory");
}
#define CP_COMMIT() asm volatile("cp.async.commit_group;" ::: "memory")
#define CP_WAIT0()  asm volatile("cp.async.wait_group 0;"  ::: "memory")

__device__ __forceinline__ void ldsm_x4(uint32_t* r, uint32_t addr) {
    asm volatile("ldmatrix.sync.aligned.m8n8.x4.shared.b16 {%0,%1,%2,%3}, [%4];"
                 : "=r"(r[0]), "=r"(r[1]), "=r"(r[2]), "=r"(r[3]) : "r"(addr));
}
__device__ __forceinline__ void ldsm_x4_t(uint32_t* r, uint32_t addr) {
    asm volatile("ldmatrix.sync.aligned.m8n8.x4.trans.shared.b16 {%0,%1,%2,%3}, [%4];"
                 : "=r"(r[0]), "=r"(r[1]), "=r"(r[2]), "=r"(r[3]) : "r"(addr));
}

__device__ __forceinline__ void mma_f16(float* d, const uint32_t* a,
                                        uint32_t b0, uint32_t b1) {
    asm volatile(
        "mma.sync.aligned.m16n8k16.row.col.f32.f16.f16.f32 "
        "{%0,%1,%2,%3}, {%4,%5,%6,%7}, {%8,%9}, {%0,%1,%2,%3};"
        : "+f"(d[0]), "+f"(d[1]), "+f"(d[2]), "+f"(d[3])
        : "r"(a[0]), "r"(a[1]), "r"(a[2]), "r"(a[3]), "r"(b0), "r"(b1));
}

// ---------------- prepass: f32 -> fp16 (rn), elementwise ----------------
__global__ void to_fp16_kernel(const float* __restrict__ src, int sel, int n4) {
    __half* dst = (sel == 0) ? g_W1h : (sel == 1) ? g_W2h : g_xh;
    int i = blockIdx.x * blockDim.x + threadIdx.x;
    const int stride = gridDim.x * blockDim.x;
    for (; i < n4; i += stride) {
        float4 v = reinterpret_cast<const float4*>(src)[i];
        __half2 h0 = __floats2half2_rn(v.x, v.y);
        __half2 h1 = __floats2half2_rn(v.z, v.w);
        uint2 o;
        o.x = reinterpret_cast<uint32_t&>(h0);
        o.y = reinterpret_cast<uint32_t&>(h1);
        reinterpret_cast<uint2*>(dst)[i] = o;
    }
}

// ---------------- staging: one 64k x 256n fp16 W chunk ----------------
__device__ __forceinline__ void stage_B(uint32_t base, const __half* src, int tid) {
    #pragma unroll
    for (int i = 0; i < 8; ++i) {
        const int u  = tid + i * 256;       // 2048 units = 64 rows x 32 x 16B
        const int k  = u >> 5;
        const int un = u & 31;
        cp16(base + k * HSB + un * 16, src + k * NDIM + un * 8);
    }
    CP_COMMIT();
}

// ---------------- main kernel ----------------
__global__ __launch_bounds__(256, 2)
void rfprism_main(const float* __restrict__ b1,
                  const float* __restrict__ b2,
                  const float* __restrict__ W3,
                  const float* __restrict__ b3,
                  float* __restrict__ out) {
    extern __shared__ char smem[];
    const uint32_t sb = smem_u32(smem);
    float* sBias1 = (float*)(smem + BIAS1_OFF);
    float* sBias2 = (float*)(smem + BIAS2_OFF);
    float* sW3v   = (float*)(smem + W3_OFF);
    float* rowsum = (float*)(smem + RS_OFF);

    const int tid  = threadIdx.x;
    const int warp = tid >> 5;          // 0..7
    const int lane = tid & 31;
    const int c    = blockIdx.y;
    const int b0   = blockIdx.x * MTILE;
    const int wm   = warp >> 2;         // 0..1 (M)
    const int wn   = warp & 3;          // 0..3 (N)
    const int g    = lane >> 2;         // 0..7
    const int tig  = lane & 3;          // 0..3

    // ldmatrix lane offset (same structure for A tiles and B-trans tiles)
    const uint32_t lmoff =
        ((((lane >> 3) & 1) * 8) + (lane & 7)) * HSB + ((lane >> 4) & 1) * 16;
    const uint32_t Aw = sb + A_OFF + (wm * 32) * HSB + lmoff;        // A base per warp
    const uint32_t Bw = lmoff + (wn * 64) * 2;                       // B offset per warp

    // ---- prologue: stage A (x tile) + W1 chunk 0; load biases/W3 ----
    #pragma unroll
    for (int i = 0; i < 8; ++i) {
        const int u   = tid + i * 256;      // 0..2047: 64 rows x 32 units
        const int row = u >> 5;
        const int un  = u & 31;
        cp16(sb + A_OFF + row * HSB + un * 16,
             g_xh + (size_t)(b0 + row) * KDIM + un * 8);
    }
    CP_COMMIT();
    stage_B(sb + B_OFF, g_W1h + (size_t)c * (KDIM * NDIM), tid);

    if (tid < 64) {
        ((float4*)sBias1)[tid] = ((const float4*)(b1 + (size_t)c * 256))[tid];
    } else if (tid < 128) {
        ((float4*)sBias2)[tid - 64] = ((const float4*)(b2 + (size_t)c * 256))[tid - 64];
    } else if (tid < 192) {
        ((float4*)sW3v)[tid - 128] = ((const float4*)(W3 + (size_t)c * 256))[tid - 128];
    } else {
        rowsum[tid - 192] = 0.0f;
    }

    float acc[2][8][4];
    #pragma unroll
    for (int m = 0; m < 2; ++m)
        #pragma unroll
        for (int t = 0; t < 8; ++t)
            #pragma unroll
            for (int r = 0; r < 4; ++r)
                acc[m][t][r] = 0.0f;

    // ---- mainloop: 8 chunks (4 per layer), ONE sync per chunk ----
    #pragma unroll 1
    for (int kk = 0; kk < 2 * NCH; ++kk) {
        CP_WAIT0();
        __syncthreads();    // chunk kk data visible; buffer (kk+1)&1 free everywhere

        // stage chunk kk+1 into the buffer freed at kk-1 (lands during compute)
        if (kk + 1 < 2 * NCH) {
            const int t2 = kk + 1;
            const __half* W = (t2 < NCH) ? g_W1h : g_W2h;
            stage_B(sb + B_OFF + (t2 & 1) * B_BYTES,
                    W + (size_t)c * (KDIM * NDIM) + (size_t)(t2 & (NCH - 1)) * (CHUNK_K * NDIM),
                    tid);
        }

        const uint32_t Bbase = sb + B_OFF + (kk & 1) * B_BYTES;
        const int kabase = (kk & (NCH - 1)) * CHUNK_K;

        #pragma unroll
        for (int s = 0; s < CHUNK_K / 16; ++s) {     // 4 k16 steps per chunk
            const int ka = kabase + s * 16;

            uint32_t bb[4][4];
            #pragma unroll
            for (int j = 0; j < 4; ++j)              // n-tiles (2 per ldsm)
                ldsm_x4_t(bb[j], Bbase + s * 16 * HSB + Bw + (j * 16) * 2);

            uint32_t a[2][4];
            #pragma unroll
            for (int m = 0; m < 2; ++m)
                ldsm_x4(a[m], Aw + m * 16 * HSB + ka * 2);

            #pragma unroll
            for (int m = 0; m < 2; ++m)
                #pragma unroll
                for (int t = 0; t < 8; ++t)
                    mma_f16(acc[m][t], a[m],
                            bb[t >> 1][(t & 1) * 2], bb[t >> 1][(t & 1) * 2 + 1]);
        }

        if (kk == NCH - 1) {
            __syncthreads();   // everyone done reading layer-1 A before overwrite
            // epilogue 1: A <- fp16(relu(acc + b1))
            #pragma unroll
            for (int m = 0; m < 2; ++m) {
                const int r0 = wm * 32 + m * 16 + g;
                const int r1 = r0 + 8;
                #pragma unroll
                for (int t = 0; t < 8; ++t) {
                    const int c0 = wn * 64 + t * 8 + 2 * tig;
                    float v00 = fmaxf(acc[m][t][0] + sBias1[c0],     0.0f);
                    float v01 = fmaxf(acc[m][t][1] + sBias1[c0 + 1], 0.0f);
                    float v10 = fmaxf(acc[m][t][2] + sBias1[c0],     0.0f);
                    float v11 = fmaxf(acc[m][t][3] + sBias1[c0 + 1], 0.0f);
                    __half2 h0 = __floats2half2_rn(v00, v01);
                    __half2 h1 = __floats2half2_rn(v10, v11);
                    *(uint32_t*)(smem + A_OFF + r0 * HSB + c0 * 2) =
                        reinterpret_cast<uint32_t&>(h0);
                    *(uint32_t*)(smem + A_OFF + r1 * HSB + c0 * 2) =
                        reinterpret_cast<uint32_t&>(h1);
                }
            }
            #pragma unroll
            for (int m = 0; m < 2; ++m)
                #pragma unroll
                for (int t = 0; t < 8; ++t)
                    #pragma unroll
                    for (int r = 0; r < 4; ++r)
                        acc[m][t][r] = 0.0f;
            // visibility for layer-2 reads: top-of-next-chunk __syncthreads
        }
    }

    // ---- epilogue 2 + layer 3: rowsum += relu(acc + b2) . W3 ----
    #pragma unroll
    for (int m = 0; m < 2; ++m) {
        const int r0 = wm * 32 + m * 16 + g;
        const int r1 = r0 + 8;
        float s0 = 0.0f, s1 = 0.0f;
        #pragma unroll
        for (int t = 0; t < 8; ++t) {
            const int c0 = wn * 64 + t * 8 + 2 * tig;
            const float w0 = sW3v[c0], w1 = sW3v[c0 + 1];
            const float bb0 = sBias2[c0], bb1 = sBias2[c0 + 1];
            s0 += fmaxf(acc[m][t][0] + bb0, 0.0f) * w0
                + fmaxf(acc[m][t][1] + bb1, 0.0f) * w1;
            s1 += fmaxf(acc[m][t][2] + bb0, 0.0f) * w0
                + fmaxf(acc[m][t][3] + bb1, 0.0f) * w1;
        }
        s0 += __shfl_xor_sync(0xffffffffu, s0, 1);
        s0 += __shfl_xor_sync(0xffffffffu, s0, 2);
        s1 += __shfl_xor_sync(0xffffffffu, s1, 1);
        s1 += __shfl_xor_sync(0xffffffffu, s1, 2);
        if (tig == 0) {
            atomicAdd(&rowsum[r0], s0);
            atomicAdd(&rowsum[r1], s1);
        }
    }

    __syncthreads();
    if (tid < MTILE)
        out[(size_t)(b0 + tid) * CSUB + c] = rowsum[tid] + b3[c];
}

extern "C" void kernel_launch(void* const* d_in, const int* in_sizes, int n_in,
                              void* d_out, int out_size) {
    (void)in_sizes; (void)n_in; (void)out_size;
    const float* x  = (const float*)d_in[0];
    const float* W1 = (const float*)d_in[1];
    const float* b1 = (const float*)d_in[2];
    const float* W2 = (const float*)d_in[3];
    const float* b2 = (const float*)d_in[4];
    const float* W3 = (const float*)d_in[5];
    const float* b3 = (const float*)d_in[6];
    float* out = (float*)d_out;

    // prepass: fp16-convert W1, W2, x into scratch
    const int nW4 = (CSUB * KDIM * NDIM) / 4;    // 4,194,304
    const int nX4 = (BATCH * KDIM) / 4;          // 131,072
    to_fp16_kernel<<<4096, 256>>>(W1, 0, nW4);
    to_fp16_kernel<<<4096, 256>>>(W2, 1, nW4);
    to_fp16_kernel<<<512, 256>>>(x,  2, nX4);

    cudaFuncSetAttribute(rfprism_main,
                         cudaFuncAttributeMaxDynamicSharedMemorySize, SMEM_BYTES);
    dim3 grid(BATCH / MTILE, CSUB);   // (32, 256)
    rfprism_main<<<grid, 256, SMEM_BYTES>>>(b1, b2, W3, b3, out);
}